// round 10
// baseline (speedup 1.0000x reference)
#include <cuda_runtime.h>
#include <cuda_fp16.h>
#include <math.h>

#define PI 3.141592653589793238462643383279502884

// ---------------- constant/table device storage (no allocation allowed) ----------
__device__ double d_FACT[40], d_RFACT[40];
__device__ double d_w[64];
__device__ double d_chi[64], d_shi[64];   // half-angle trig, input betas
__device__ double d_cho[32], d_sho[32];   // output betas
__device__ double d_chg[4],  d_shg[4];    // kernel-grid betas

__device__ float  g_W[64 * 16 * 16];          // [j][l][mi] = w_j d^l_{m,0}(beta_in_j), m>=0
__device__ float  g_D2[31 * 31 * 32 * 16];    // [md][nd][k][l]; only md>=15 rows written
__device__ float2 g_FKc[32 * 16 * 31];        // conj(FK) [g][l][md]
__device__ float2 g_EOUT[31 * 32];            // e^{+2pi i n c/32}   [nd][c]
__device__ float2 g_EIN16[16 * 64];           // e^{-2pi i m a/64}   [m][a], m>=0
__device__ float2 g_EB[16 * 32];              // (m?2:1) e^{+2pi i m a/32} [mi][a]

__device__ float2 g_xm[8 * 64 * 16 * 64];     // [b][j][mi][f]
__device__ float2 g_xhat[16 * 128 * 64];      // [l][(mi*8+b)][f]
__device__ float2 g_khc[16 * 31 * 64 * 128];  // [l][nd][i][o]
__device__ float2 g_z[16 * 16 * 31 * 1024];   // [l][mi][nd][bo]
__device__ __half2 g_fmnH[32 * 256 * 16 * 124]; // [k][boq][mi][nd*4+q], fp16 complex

// ---------------- helpers ----------------
__device__ __forceinline__ double ipow(double x, int e) {
    double r = 1.0, b = x;
    while (e) { if (e & 1) r *= b; b *= b; e >>= 1; }
    return r;
}

// Wigner small-d with factorial tables staged in shared memory
__device__ double wigS(int l, int m1, int m2, double ch, double sh,
                       const double* __restrict__ sF, const double* __restrict__ sRF) {
    int k0 = max(0, m2 - m1), k1 = min(l + m2, l - m1);
    if (k1 < k0) return 0.0;
    double num = sqrt(sF[l + m1] * sF[l - m1] * sF[l + m2] * sF[l - m2]);
    double cp = ipow(ch, 2 * l + m2 - m1 - 2 * k0);
    double sp = ipow(sh, m1 - m2 + 2 * k0);
    double c2i = 1.0 / (ch * ch), s2 = sh * sh;
    double sum = 0.0;
    for (int k = k0; k <= k1; ++k) {
        double t = num * sRF[l + m2 - k] * sRF[k] * sRF[m1 - m2 + k] * sRF[l - m1 - k] * cp * sp;
        sum += ((m1 - m2 + k) & 1) ? -t : t;
        cp *= c2i; sp *= s2;
    }
    return sum;
}

__device__ __forceinline__ void cfma(float2& c, float2 a, float2 b) {
    c.x += a.x * b.x - a.y * b.y;
    c.y += a.x * b.y + a.y * b.x;
}

// ---------------- P0: scalars + twiddle tables ----------------
__global__ void k_p0() {
    int t = threadIdx.x;
    if (t == 0) {
        double f = 1.0;
        d_FACT[0] = 1.0; d_RFACT[0] = 1.0;
        for (int n = 1; n < 40; ++n) { f *= (double)n; d_FACT[n] = f; d_RFACT[n] = 1.0 / f; }
    }
    if (t < 64) {
        double beta = PI * (2 * t + 0.5) / 128.0;
        d_chi[t] = cos(0.5 * beta); d_shi[t] = sin(0.5 * beta);
        double s = 0.0;
        for (int kk = 0; kk < 32; ++kk) s += sin(beta * (2 * kk + 1)) / (double)(2 * kk + 1);
        d_w[t] = (2.0 * PI / 64.0) * (2.0 / 32.0) * sin(beta) * s;
    }
    if (t < 32) {
        double beta = PI * (2 * t + 0.5) / 64.0;
        d_cho[t] = cos(0.5 * beta); d_sho[t] = sin(0.5 * beta);
    }
    if (t < 4) {
        double beta = (PI / 8.0) * (double)(t + 1) / 4.0;
        d_chg[t] = cos(0.5 * beta); d_shg[t] = sin(0.5 * beta);
    }
    for (int u = t; u < 16 * 64; u += 256) {
        int m = u >> 6, a = u & 63;
        double ang = -2.0 * PI * (double)m * (double)a / 64.0;
        g_EIN16[u] = make_float2((float)cos(ang), (float)sin(ang));
    }
    for (int u = t; u < 31 * 32; u += 256) {
        int nd = u >> 5, c = u & 31;
        double ang = 2.0 * PI * (double)(nd - 15) * (double)c / 32.0;
        g_EOUT[u] = make_float2((float)cos(ang), (float)sin(ang));
    }
    for (int u = t; u < 16 * 32; u += 256) {
        int mi = u >> 5, a = u & 31;
        double ang = 2.0 * PI * (double)mi * (double)a / 32.0;
        double sc = mi ? 2.0 : 1.0;
        g_EB[u] = make_float2((float)(sc * cos(ang)), (float)(sc * sin(ang)));
    }
}

// ---------------- K_TABF: W_ANA + FKc (fast path tables) ----------------
__global__ void k_tabF() {
    __shared__ double sF[40], sRF[40];
    int bx = blockIdx.x, t = threadIdx.x;
    if (t < 40) { sF[t] = d_FACT[t]; sRF[t] = d_RFACT[t]; }
    __syncthreads();
    if (bx < 64) {
        int idx = bx * 256 + t;
        int mi = idx & 15, l = (idx >> 4) & 15, j = idx >> 8;
        float v = 0.f;
        if (mi <= l) v = (float)(d_w[j] * wigS(l, mi, 0, d_chi[j], d_shi[j], sF, sRF));
        g_W[idx] = v;
    } else {
        int idx = (bx - 64) * 256 + t;
        int md = idx % 31, l = (idx / 31) % 16, g = idx / 496;
        int m = md - 15;
        float2 v = make_float2(0.f, 0.f);
        if (m >= -l && m <= l) {
            int ib = g >> 3, ia = g & 7;
            double d = wigS(l, m, 0, d_chg[ib], d_shg[ib], sF, sRF);
            double ang = (double)m * (2.0 * PI * (double)ia / 8.0);
            v = make_float2((float)(d * cos(ang)), (float)(-d * sin(ang)));
        }
        g_FKc[idx] = v;
    }
}

// ---------------- K_TABD: D2 table, warp-per-(m,nd,l), lane = beta ----------
__global__ void __launch_bounds__(256) k_tabD() {
    __shared__ double sF[40], sRF[40], sch[32], ssh[32];
    int t = threadIdx.x;
    if (t < 40) { sF[t] = d_FACT[t]; sRF[t] = d_RFACT[t]; }
    if (t >= 64 && t < 96)  sch[t - 64] = d_cho[t - 64];
    if (t >= 96 && t < 128) ssh[t - 96] = d_sho[t - 96];
    __syncthreads();
    int w = blockIdx.x * 8 + (t >> 5);
    int lane = t & 31;
    int m = w / 496;
    int rem = w - m * 496;
    int nd = rem >> 4;     // 0..30
    int l = rem & 15;
    int n = nd - 15;
    if (m > l || abs(n) > l) return;
    if (n >= 0 && n > m) return;     // covered by (n,m) thread
    double d = (double)(2 * l + 1) * wigS(l, m, n, sch[lane], ssh[lane], sF, sRF);
    float fd = (float)d;
    g_D2[(((m + 15) * 31 + nd) * 32 + lane) * 16 + l] = fd;
    if (n >= 0 && n < m) {
        float ds = ((m - n) & 1) ? -fd : fd;   // d^l_{n,m} = (-1)^{m-n} d^l_{m,n}
        g_D2[(((n + 15) * 31 + (m + 15)) * 32 + lane) * 16 + l] = ds;
    }
}

// ---------------- KA1: alpha-DFT with alpha-parity fold ----------------
__global__ void __launch_bounds__(256) k_a1(const float* __restrict__ x) {
    __shared__ float xeS[64 * 33];
    __shared__ float xoS[64 * 33];
    __shared__ float2 eS[16 * 32];
    int b = blockIdx.x >> 6, jb = blockIdx.x & 63;
    int t = threadIdx.x;
    for (int u = t; u < 2048; u += 256) {
        int f = u >> 5, a = u & 31;
        const float* xp = x + ((b * 64 + f) * 64 + jb) * 64;
        float lo = xp[a], hi = xp[a + 32];
        xeS[f * 33 + a] = lo + hi;
        xoS[f * 33 + a] = lo - hi;
    }
    for (int u = t; u < 512; u += 256) {
        int m = u >> 5, a = u & 31;
        eS[u] = g_EIN16[m * 64 + a];
    }
    __syncthreads();
    int f = t & 63, mg = t >> 6;
    float2 acc[4];
#pragma unroll
    for (int j = 0; j < 4; ++j) acc[j] = make_float2(0.f, 0.f);
    const float* xe = &xeS[f * 33];
    const float* xo = &xoS[f * 33];
#pragma unroll 8
    for (int a = 0; a < 32; ++a) {
        float ve = xe[a], vo = xo[a];
#pragma unroll
        for (int j = 0; j < 4; ++j) {
            float v = (j & 1) ? vo : ve;
            float2 e = eS[(mg * 4 + j) * 32 + a];
            acc[j].x += v * e.x; acc[j].y += v * e.y;
        }
    }
#pragma unroll
    for (int j = 0; j < 4; ++j)
        g_xm[((b * 64 + jb) * 16 + mg * 4 + j) * 64 + f] = acc[j];
}

// ---------------- KA2: beta quadrature, 4-way j-split + smem reduce ------------
__global__ void __launch_bounds__(256) k_a2() {
    int mi = blockIdx.x, b = blockIdx.y;
    int t = threadIdx.x, f = t & 63, jh = t >> 6;
    __shared__ float Ws[64 * 16];
    __shared__ float2 red[3][16][64];
    for (int u = t; u < 1024; u += 256) {
        int j = u >> 4, l = u & 15;
        Ws[u] = g_W[(j * 16 + l) * 16 + mi];
    }
    __syncthreads();
    float2 acc[16];
#pragma unroll
    for (int l = 0; l < 16; ++l) acc[l] = make_float2(0.f, 0.f);
    for (int jj = 0; jj < 16; ++jj) {
        int j = jh * 16 + jj;
        float2 v = g_xm[((b * 64 + j) * 16 + mi) * 64 + f];
#pragma unroll
        for (int l = 0; l < 16; ++l) {
            float w = Ws[j * 16 + l];
            acc[l].x += w * v.x; acc[l].y += w * v.y;
        }
    }
    if (jh > 0) {
#pragma unroll
        for (int l = 0; l < 16; ++l) red[jh - 1][l][f] = acc[l];
    }
    __syncthreads();
    if (jh == 0) {
#pragma unroll
        for (int l = 0; l < 16; ++l) {
            float2 r0 = red[0][l][f], r1 = red[1][l][f], r2 = red[2][l][f];
            g_xhat[(l * 128 + mi * 8 + b) * 64 + f] =
                make_float2(acc[l].x + r0.x + r1.x + r2.x,
                            acc[l].y + r0.y + r1.y + r2.y);
        }
    }
}

// ---------------- KB: khc = conj(kh) ----------------
__global__ void __launch_bounds__(256) k_b(const float* __restrict__ ker) {
    __shared__ float ks[64 * 33];
    int i = blockIdx.x >> 1, half = blockIdx.x & 1;
    int t = threadIdx.x;
    for (int u = t; u < 2048; u += 256) {
        int ol = u >> 5, g = u & 31;
        ks[ol * 33 + g] = ker[(i * 128 + half * 64 + ol) * 32 + g];
    }
    __syncthreads();
    const float SC = 0.002762135864009951f;   // 1/sqrt(131072)
    int ol = t & 63, pg = t >> 6;
    for (int it = 0; it < 64; ++it) {
        int p = it * 4 + pg;
        int l = (int)floorf(sqrtf((float)p + 0.5f));
        int nd = 15 - l + (p - l * l);
        float2 acc = make_float2(0.f, 0.f);
#pragma unroll 8
        for (int g = 0; g < 32; ++g) {
            float kv = ks[ol * 33 + g];
            float2 fv = g_FKc[(g * 16 + l) * 31 + nd];
            acc.x += kv * fv.x; acc.y += kv * fv.y;
        }
        g_khc[((l * 31 + nd) * 64 + i) * 128 + half * 64 + ol] =
            make_float2(SC * acc.x, SC * acc.y);
    }
}

// ---------------- KC: per-degree complex GEMM, 64x64 tile, 4x4 micro ----------
__global__ void __launch_bounds__(256) k_c() {
    int l = blockIdx.z;
    int rows = (l + 1) * 8;
    int nT = (2 * l + 1) * 2;
    if ((int)blockIdx.x >= nT) return;
    int row0 = blockIdx.y * 64;
    if (row0 >= rows) return;
    int ndi = blockIdx.x >> 1;
    int o0 = (blockIdx.x & 1) * 64;
    int nd = 15 - l + ndi;
    __shared__ float2 As[16 * 65];
    __shared__ float2 Bs[16 * 64];
    int t = threadIdx.x, tx = t & 15, ty = t >> 4;
    float2 c[4][4] = {};
    for (int kc = 0; kc < 64; kc += 16) {
        {
            int kk = t & 15, r0 = t >> 4;
#pragma unroll
            for (int p = 0; p < 4; ++p)
                As[kk * 65 + r0 + 16 * p] = g_xhat[(l * 128 + row0 + r0 + 16 * p) * 64 + kc + kk];
        }
        {
            int cc = t & 63, kb = t >> 6;
#pragma unroll
            for (int p = 0; p < 4; ++p)
                Bs[(kb + 4 * p) * 64 + cc] = g_khc[((l * 31 + nd) * 64 + kc + kb + 4 * p) * 128 + o0 + cc];
        }
        __syncthreads();
#pragma unroll
        for (int kk = 0; kk < 16; ++kk) {
            float2 a[4], bv[4];
#pragma unroll
            for (int i = 0; i < 4; ++i) a[i] = As[kk * 65 + ty + 16 * i];
#pragma unroll
            for (int j = 0; j < 4; ++j) bv[j] = Bs[kk * 64 + tx + 16 * j];
#pragma unroll
            for (int i = 0; i < 4; ++i)
#pragma unroll
                for (int j = 0; j < 4; ++j) cfma(c[i][j], a[i], bv[j]);
        }
        __syncthreads();
    }
#pragma unroll
    for (int i = 0; i < 4; ++i) {
        int R = row0 + ty + 16 * i;
        if (R < rows) {
            int base = ((l * 16 + (R >> 3)) * 31 + nd) * 1024 + (R & 7) * 128 + o0;
#pragma unroll
            for (int j = 0; j < 4; ++j) g_z[base + tx + 16 * j] = c[i][j];
        }
    }
}

// ---------------- KD: fmn = sum_l D2 * z, lmin-templated sparsity -------------
template<int LMIN>
__device__ __forceinline__ void kd_body(const float* __restrict__ Ds,
                                        int bo0, int nd, int mi, int t) {
    constexpr int NLz = 16 - LMIN;
    float2 zr[NLz];
#pragma unroll
    for (int u = 0; u < NLz; ++u)
        zr[u] = g_z[(((LMIN + u) * 16 + mi) * 31 + nd) * 1024 + bo0 + t];
    int bo = bo0 + t;
    int baseq = ((bo >> 2) * 16 + mi) * 124 + nd * 4 + (bo & 3);
    for (int k = 0; k < 32; ++k) {
        float2 acc = make_float2(0.f, 0.f);
#pragma unroll
        for (int u = 0; u < NLz; ++u) {
            float d = Ds[k * 16 + LMIN + u];
            acc.x += d * zr[u].x; acc.y += d * zr[u].y;
        }
        g_fmnH[(size_t)k * 507904 + baseq] = __floats2half2_rn(acc.x, acc.y);
    }
}

__global__ void __launch_bounds__(256) k_d() {
    int bo0 = blockIdx.x * 256, nd = blockIdx.y, mi = blockIdx.z;
    int t = threadIdx.x;
    int n = nd - 15;
    int lmin = max(mi, abs(n));
    __shared__ float Ds[512];
    for (int u = t; u < 512; u += 256)
        Ds[u] = g_D2[((mi + 15) * 31 + nd) * 512 + u];
    __syncthreads();
    switch (lmin) {
        case 0:  kd_body<0>(Ds, bo0, nd, mi, t);  break;
        case 1:  kd_body<1>(Ds, bo0, nd, mi, t);  break;
        case 2:  kd_body<2>(Ds, bo0, nd, mi, t);  break;
        case 3:  kd_body<3>(Ds, bo0, nd, mi, t);  break;
        case 4:  kd_body<4>(Ds, bo0, nd, mi, t);  break;
        case 5:  kd_body<5>(Ds, bo0, nd, mi, t);  break;
        case 6:  kd_body<6>(Ds, bo0, nd, mi, t);  break;
        case 7:  kd_body<7>(Ds, bo0, nd, mi, t);  break;
        case 8:  kd_body<8>(Ds, bo0, nd, mi, t);  break;
        case 9:  kd_body<9>(Ds, bo0, nd, mi, t);  break;
        case 10: kd_body<10>(Ds, bo0, nd, mi, t); break;
        case 11: kd_body<11>(Ds, bo0, nd, mi, t); break;
        case 12: kd_body<12>(Ds, bo0, nd, mi, t); break;
        case 13: kd_body<13>(Ds, bo0, nd, mi, t); break;
        case 14: kd_body<14>(Ds, bo0, nd, mi, t); break;
        default: kd_body<15>(Ds, bo0, nd, mi, t); break;
    }
}

// ---------------- KEF: fused n-DFT (radix-4 over c) + real m-DFT ----------------
__global__ void __launch_bounds__(256) k_ef(float* __restrict__ out, const float* __restrict__ bias) {
    int boq = blockIdx.x, k = blockIdx.y;
    __shared__ __align__(16) float2 fS[16 * 124];
    __shared__ float2 Hs[4 * 16 * 32];
    __shared__ float2 ES1[31 * 8];       // e^{+2pi i n c/32}, c<8
    __shared__ float2 EBs[16 * 32];
    int t = threadIdx.x;
    {
        // fmn tile in fp16: 1984 complex = 992 uint2 (2 half2 each)
        const uint2* src = (const uint2*)(g_fmnH + (size_t)(k * 256 + boq) * 1984);
        for (int u = t; u < 992; u += 256) {
            uint2 v = src[u];
            __half2 h0 = *(__half2*)&v.x;
            __half2 h1 = *(__half2*)&v.y;
            fS[2 * u]     = __half22float2(h0);
            fS[2 * u + 1] = __half22float2(h1);
        }
    }
    for (int u = t; u < 248; u += 256) {
        int nd = u >> 3, c = u & 7;
        ES1[u] = g_EOUT[nd * 32 + c];
    }
    for (int u = t; u < 512; u += 256) EBs[u] = g_EB[u];
    __syncthreads();
    // stage 1: H[mi][c'] = sum_nd f e_n(c'); c' in {c, c+8, c+16, c+24} via n mod 4 groups
    {
        int mi = t >> 4, q2 = (t >> 3) & 1, c = t & 7;
        float2 G[2][4];
#pragma unroll
        for (int qq = 0; qq < 2; ++qq)
#pragma unroll
            for (int r = 0; r < 4; ++r) G[qq][r] = make_float2(0.f, 0.f);
        const float4* f4 = (const float4*)(fS + mi * 124);
#pragma unroll
        for (int nd = 0; nd < 31; ++nd) {
            float2 e = ES1[nd * 8 + c];
            float4 fv = f4[nd * 2 + q2];        // q = 2*q2, 2*q2+1
            float2 f0 = make_float2(fv.x, fv.y), f1 = make_float2(fv.z, fv.w);
            int r = (nd + 1) & 3;               // i^n = i^r, n = nd-15
            cfma(G[0][r], f0, e);
            cfma(G[1][r], f1, e);
        }
#pragma unroll
        for (int qq = 0; qq < 2; ++qq) {
            int q = q2 * 2 + qq;
            float2 g0 = G[qq][0], g1 = G[qq][1], g2 = G[qq][2], g3 = G[qq][3];
            float2* Hr = &Hs[(q * 16 + mi) * 32];
            Hr[c]      = make_float2(g0.x + g1.x + g2.x + g3.x, g0.y + g1.y + g2.y + g3.y);
            Hr[c + 8]  = make_float2(g0.x - g1.y - g2.x + g3.y, g0.y + g1.x - g2.y - g3.x);
            Hr[c + 16] = make_float2(g0.x - g1.x + g2.x - g3.x, g0.y - g1.y + g2.y - g3.y);
            Hr[c + 24] = make_float2(g0.x + g1.y - g2.x - g3.y, g0.y - g1.x - g2.y + g3.x);
        }
    }
    __syncthreads();
    // stage 2: out[a][c] = sum_mi w_mi Re(H e^{i2pi mi a/32}); a+16 via m-parity
    {
        int c = t & 31, q = (t >> 5) & 3, ag = t >> 7;
        float E[8] = {}, O[8] = {};
#pragma unroll
        for (int mi = 0; mi < 16; ++mi) {
            float2 h = Hs[(q * 16 + mi) * 32 + c];
#pragma unroll
            for (int j = 0; j < 8; ++j) {
                float2 e = EBs[mi * 32 + ag * 8 + j];
                float re = h.x * e.x - h.y * e.y;
                if (mi & 1) O[j] += re; else E[j] += re;
            }
        }
        int bo = boq * 4 + q;
        float bv = bias[bo & 127];
        size_t base = ((size_t)(bo * 32 + k)) * 1024 + c;
#pragma unroll
        for (int j = 0; j < 8; ++j) {
            int a = ag * 8 + j;
            out[base + a * 32]        = E[j] + O[j] + bv;
            out[base + (a + 16) * 32] = E[j] - O[j] + bv;
        }
    }
}

// ---------------- stream/event fork-join (created at static init) -------------
static cudaStream_t g_s1 = 0;
static cudaEvent_t g_eP0 = 0, g_eTabF = 0, g_eA2 = 0, g_eTabD = 0;
static bool g_streamOK = false;
namespace {
struct StreamInit {
    StreamInit() {
        bool ok = (cudaStreamCreateWithFlags(&g_s1, cudaStreamNonBlocking) == cudaSuccess);
        ok = ok && (cudaEventCreateWithFlags(&g_eP0, cudaEventDisableTiming) == cudaSuccess);
        ok = ok && (cudaEventCreateWithFlags(&g_eTabF, cudaEventDisableTiming) == cudaSuccess);
        ok = ok && (cudaEventCreateWithFlags(&g_eA2, cudaEventDisableTiming) == cudaSuccess);
        ok = ok && (cudaEventCreateWithFlags(&g_eTabD, cudaEventDisableTiming) == cudaSuccess);
        g_streamOK = ok;
    }
};
static StreamInit g_streamInit;
}

// ---------------- launch ----------------
extern "C" void kernel_launch(void* const* d_in, const int* in_sizes, int n_in,
                              void* d_out, int out_size) {
    const float* x    = (const float*)d_in[0];
    const float* ker  = (const float*)d_in[1];
    const float* bias = (const float*)d_in[2];
    float* out = (float*)d_out;

    if (g_streamOK) {
        // main: p0 -> tabF -> b -> [wait a2] c -> [wait tabD] d -> ef
        // s1:   [wait p0] a1 -> [wait tabF] a2 -> tabD
        k_p0<<<1, 256>>>();
        cudaEventRecord(g_eP0, 0);
        cudaStreamWaitEvent(g_s1, g_eP0, 0);
        k_a1<<<512, 256, 0, g_s1>>>(x);
        k_tabF<<<126, 256>>>();
        cudaEventRecord(g_eTabF, 0);
        cudaStreamWaitEvent(g_s1, g_eTabF, 0);
        k_a2<<<dim3(16, 8), 256, 0, g_s1>>>();
        cudaEventRecord(g_eA2, g_s1);
        k_tabD<<<992, 256, 0, g_s1>>>();
        cudaEventRecord(g_eTabD, g_s1);
        k_b<<<128, 256>>>(ker);
        cudaStreamWaitEvent(0, g_eA2, 0);
        k_c<<<dim3(62, 2, 16), 256>>>();
        cudaStreamWaitEvent(0, g_eTabD, 0);
        k_d<<<dim3(4, 31, 16), 256>>>();
        k_ef<<<dim3(256, 32), 256>>>(out, bias);
    } else {
        k_p0<<<1, 256>>>();
        k_tabF<<<126, 256>>>();
        k_tabD<<<992, 256>>>();
        k_a1<<<512, 256>>>(x);
        k_a2<<<dim3(16, 8), 256>>>();
        k_b<<<128, 256>>>(ker);
        k_c<<<dim3(62, 2, 16), 256>>>();
        k_d<<<dim3(4, 31, 16), 256>>>();
        k_ef<<<dim3(256, 32), 256>>>(out, bias);
    }
    (void)in_sizes; (void)n_in; (void)out_size;
}

// round 11
// speedup vs baseline: 1.0845x; 1.0845x over previous
#include <cuda_runtime.h>
#include <math.h>

#define PI 3.141592653589793238462643383279502884

// ---------------- constant/table device storage (no allocation allowed) ----------
__device__ double d_FACT[40], d_RFACT[40];
__device__ double d_w[64];
__device__ double d_chi[64], d_shi[64];   // half-angle trig, input betas
__device__ double d_cho[32], d_sho[32];   // output betas
__device__ double d_chg[4],  d_shg[4];    // kernel-grid betas

__device__ float  g_W[64 * 16 * 16];          // [j][l][mi] = w_j d^l_{m,0}(beta_in_j), m>=0
__device__ float  g_D2[31 * 31 * 32 * 16];    // [md][nd][k][l]; only md>=15 rows written
__device__ float2 g_FKc[32 * 16 * 31];        // conj(FK) [g][l][md]
__device__ float2 g_EOUT[31 * 32];            // e^{+2pi i n c/32}   [nd][c]
__device__ float2 g_EIN16[16 * 64];           // e^{-2pi i m a/64}   [m][a], m>=0
__device__ float2 g_EB[16 * 32];              // (m?2:1) e^{+2pi i m a/32} [mi][a]

__device__ float2 g_xm[8 * 64 * 16 * 64];     // [b][j][mi][f]
__device__ float2 g_xhat[16 * 128 * 64];      // [l][(mi*8+b)][f]
__device__ float2 g_khc[16 * 31 * 64 * 128];  // [l][nd][i][o]
__device__ float2 g_z[16 * 16 * 31 * 1024];   // [l][mi][nd][bo]
__device__ float2 g_fmn[32 * 256 * 16 * 124]; // [k][boq][mi][nd*4+q]

// ---------------- helpers ----------------
__device__ __forceinline__ double ipow(double x, int e) {
    double r = 1.0, b = x;
    while (e) { if (e & 1) r *= b; b *= b; e >>= 1; }
    return r;
}

// Wigner small-d with factorial tables staged in shared memory
__device__ double wigS(int l, int m1, int m2, double ch, double sh,
                       const double* __restrict__ sF, const double* __restrict__ sRF) {
    int k0 = max(0, m2 - m1), k1 = min(l + m2, l - m1);
    if (k1 < k0) return 0.0;
    double num = sqrt(sF[l + m1] * sF[l - m1] * sF[l + m2] * sF[l - m2]);
    double cp = ipow(ch, 2 * l + m2 - m1 - 2 * k0);
    double sp = ipow(sh, m1 - m2 + 2 * k0);
    double c2i = 1.0 / (ch * ch), s2 = sh * sh;
    double sum = 0.0;
    for (int k = k0; k <= k1; ++k) {
        double t = num * sRF[l + m2 - k] * sRF[k] * sRF[m1 - m2 + k] * sRF[l - m1 - k] * cp * sp;
        sum += ((m1 - m2 + k) & 1) ? -t : t;
        cp *= c2i; sp *= s2;
    }
    return sum;
}

__device__ __forceinline__ void cfma(float2& c, float2 a, float2 b) {
    c.x += a.x * b.x - a.y * b.y;
    c.y += a.x * b.y + a.y * b.x;
}

// ---------------- P0: scalars + twiddle tables ----------------
__global__ void k_p0() {
    int t = threadIdx.x;
    if (t == 0) {
        double f = 1.0;
        d_FACT[0] = 1.0; d_RFACT[0] = 1.0;
        for (int n = 1; n < 40; ++n) { f *= (double)n; d_FACT[n] = f; d_RFACT[n] = 1.0 / f; }
    }
    if (t < 64) {
        double beta = PI * (2 * t + 0.5) / 128.0;
        d_chi[t] = cos(0.5 * beta); d_shi[t] = sin(0.5 * beta);
        double s = 0.0;
        for (int kk = 0; kk < 32; ++kk) s += sin(beta * (2 * kk + 1)) / (double)(2 * kk + 1);
        d_w[t] = (2.0 * PI / 64.0) * (2.0 / 32.0) * sin(beta) * s;
    }
    if (t < 32) {
        double beta = PI * (2 * t + 0.5) / 64.0;
        d_cho[t] = cos(0.5 * beta); d_sho[t] = sin(0.5 * beta);
    }
    if (t < 4) {
        double beta = (PI / 8.0) * (double)(t + 1) / 4.0;
        d_chg[t] = cos(0.5 * beta); d_shg[t] = sin(0.5 * beta);
    }
    for (int u = t; u < 16 * 64; u += 256) {
        int m = u >> 6, a = u & 63;
        double ang = -2.0 * PI * (double)m * (double)a / 64.0;
        g_EIN16[u] = make_float2((float)cos(ang), (float)sin(ang));
    }
    for (int u = t; u < 31 * 32; u += 256) {
        int nd = u >> 5, c = u & 31;
        double ang = 2.0 * PI * (double)(nd - 15) * (double)c / 32.0;
        g_EOUT[u] = make_float2((float)cos(ang), (float)sin(ang));
    }
    for (int u = t; u < 16 * 32; u += 256) {
        int mi = u >> 5, a = u & 31;
        double ang = 2.0 * PI * (double)mi * (double)a / 32.0;
        double sc = mi ? 2.0 : 1.0;
        g_EB[u] = make_float2((float)(sc * cos(ang)), (float)(sc * sin(ang)));
    }
}

// ---------------- K_TABF: W_ANA + FKc (fast path tables) ----------------
__global__ void k_tabF() {
    __shared__ double sF[40], sRF[40];
    int bx = blockIdx.x, t = threadIdx.x;
    if (t < 40) { sF[t] = d_FACT[t]; sRF[t] = d_RFACT[t]; }
    __syncthreads();
    if (bx < 64) {
        int idx = bx * 256 + t;
        int mi = idx & 15, l = (idx >> 4) & 15, j = idx >> 8;
        float v = 0.f;
        if (mi <= l) v = (float)(d_w[j] * wigS(l, mi, 0, d_chi[j], d_shi[j], sF, sRF));
        g_W[idx] = v;
    } else {
        int idx = (bx - 64) * 256 + t;
        int md = idx % 31, l = (idx / 31) % 16, g = idx / 496;
        int m = md - 15;
        float2 v = make_float2(0.f, 0.f);
        if (m >= -l && m <= l) {
            int ib = g >> 3, ia = g & 7;
            double d = wigS(l, m, 0, d_chg[ib], d_shg[ib], sF, sRF);
            double ang = (double)m * (2.0 * PI * (double)ia / 8.0);
            v = make_float2((float)(d * cos(ang)), (float)(-d * sin(ang)));
        }
        g_FKc[idx] = v;
    }
}

// ---------------- K_TABD: D2 table, warp-per-(m,nd,l), lane = beta ----------
__global__ void __launch_bounds__(256) k_tabD() {
    __shared__ double sF[40], sRF[40], sch[32], ssh[32];
    int t = threadIdx.x;
    if (t < 40) { sF[t] = d_FACT[t]; sRF[t] = d_RFACT[t]; }
    if (t >= 64 && t < 96)  sch[t - 64] = d_cho[t - 64];
    if (t >= 96 && t < 128) ssh[t - 96] = d_sho[t - 96];
    __syncthreads();
    int w = blockIdx.x * 8 + (t >> 5);
    int lane = t & 31;
    int m = w / 496;
    int rem = w - m * 496;
    int nd = rem >> 4;     // 0..30
    int l = rem & 15;
    int n = nd - 15;
    if (m > l || abs(n) > l) return;
    if (n >= 0 && n > m) return;     // covered by (n,m) thread
    double d = (double)(2 * l + 1) * wigS(l, m, n, sch[lane], ssh[lane], sF, sRF);
    float fd = (float)d;
    g_D2[(((m + 15) * 31 + nd) * 32 + lane) * 16 + l] = fd;
    if (n >= 0 && n < m) {
        float ds = ((m - n) & 1) ? -fd : fd;   // d^l_{n,m} = (-1)^{m-n} d^l_{m,n}
        g_D2[(((n + 15) * 31 + (m + 15)) * 32 + lane) * 16 + l] = ds;
    }
}

// ---------------- KA1: alpha-DFT with alpha-parity fold ----------------
__global__ void __launch_bounds__(256) k_a1(const float* __restrict__ x) {
    __shared__ float xeS[64 * 33];
    __shared__ float xoS[64 * 33];
    __shared__ float2 eS[16 * 32];
    int b = blockIdx.x >> 6, jb = blockIdx.x & 63;
    int t = threadIdx.x;
    for (int u = t; u < 2048; u += 256) {
        int f = u >> 5, a = u & 31;
        const float* xp = x + ((b * 64 + f) * 64 + jb) * 64;
        float lo = xp[a], hi = xp[a + 32];
        xeS[f * 33 + a] = lo + hi;
        xoS[f * 33 + a] = lo - hi;
    }
    for (int u = t; u < 512; u += 256) {
        int m = u >> 5, a = u & 31;
        eS[u] = g_EIN16[m * 64 + a];
    }
    __syncthreads();
    int f = t & 63, mg = t >> 6;
    float2 acc[4];
#pragma unroll
    for (int j = 0; j < 4; ++j) acc[j] = make_float2(0.f, 0.f);
    const float* xe = &xeS[f * 33];
    const float* xo = &xoS[f * 33];
#pragma unroll 8
    for (int a = 0; a < 32; ++a) {
        float ve = xe[a], vo = xo[a];
#pragma unroll
        for (int j = 0; j < 4; ++j) {
            float v = (j & 1) ? vo : ve;
            float2 e = eS[(mg * 4 + j) * 32 + a];
            acc[j].x += v * e.x; acc[j].y += v * e.y;
        }
    }
#pragma unroll
    for (int j = 0; j < 4; ++j)
        g_xm[((b * 64 + jb) * 16 + mg * 4 + j) * 64 + f] = acc[j];
}

// ---------------- KA2: beta quadrature, 4-way j-split + smem reduce ------------
__global__ void __launch_bounds__(256) k_a2() {
    int mi = blockIdx.x, b = blockIdx.y;
    int t = threadIdx.x, f = t & 63, jh = t >> 6;
    __shared__ float Ws[64 * 16];
    __shared__ float2 red[3][16][64];
    for (int u = t; u < 1024; u += 256) {
        int j = u >> 4, l = u & 15;
        Ws[u] = g_W[(j * 16 + l) * 16 + mi];
    }
    __syncthreads();
    float2 acc[16];
#pragma unroll
    for (int l = 0; l < 16; ++l) acc[l] = make_float2(0.f, 0.f);
    for (int jj = 0; jj < 16; ++jj) {
        int j = jh * 16 + jj;
        float2 v = g_xm[((b * 64 + j) * 16 + mi) * 64 + f];
#pragma unroll
        for (int l = 0; l < 16; ++l) {
            float w = Ws[j * 16 + l];
            acc[l].x += w * v.x; acc[l].y += w * v.y;
        }
    }
    if (jh > 0) {
#pragma unroll
        for (int l = 0; l < 16; ++l) red[jh - 1][l][f] = acc[l];
    }
    __syncthreads();
    if (jh == 0) {
#pragma unroll
        for (int l = 0; l < 16; ++l) {
            float2 r0 = red[0][l][f], r1 = red[1][l][f], r2 = red[2][l][f];
            g_xhat[(l * 128 + mi * 8 + b) * 64 + f] =
                make_float2(acc[l].x + r0.x + r1.x + r2.x,
                            acc[l].y + r0.y + r1.y + r2.y);
        }
    }
}

// ---------------- KB: khc = conj(kh) ----------------
__global__ void __launch_bounds__(256) k_b(const float* __restrict__ ker) {
    __shared__ float ks[64 * 33];
    int i = blockIdx.x >> 1, half = blockIdx.x & 1;
    int t = threadIdx.x;
    for (int u = t; u < 2048; u += 256) {
        int ol = u >> 5, g = u & 31;
        ks[ol * 33 + g] = ker[(i * 128 + half * 64 + ol) * 32 + g];
    }
    __syncthreads();
    const float SC = 0.002762135864009951f;   // 1/sqrt(131072)
    int ol = t & 63, pg = t >> 6;
    for (int it = 0; it < 64; ++it) {
        int p = it * 4 + pg;
        int l = (int)floorf(sqrtf((float)p + 0.5f));
        int nd = 15 - l + (p - l * l);
        float2 acc = make_float2(0.f, 0.f);
#pragma unroll 8
        for (int g = 0; g < 32; ++g) {
            float kv = ks[ol * 33 + g];
            float2 fv = g_FKc[(g * 16 + l) * 31 + nd];
            acc.x += kv * fv.x; acc.y += kv * fv.y;
        }
        g_khc[((l * 31 + nd) * 64 + i) * 128 + half * 64 + ol] =
            make_float2(SC * acc.x, SC * acc.y);
    }
}

// ---------------- KC: per-degree complex GEMM, 64x64 tile, 4x4 micro ----------
__global__ void __launch_bounds__(256) k_c() {
    int l = blockIdx.z;
    int rows = (l + 1) * 8;
    int nT = (2 * l + 1) * 2;
    if ((int)blockIdx.x >= nT) return;
    int row0 = blockIdx.y * 64;
    if (row0 >= rows) return;
    int ndi = blockIdx.x >> 1;
    int o0 = (blockIdx.x & 1) * 64;
    int nd = 15 - l + ndi;
    __shared__ float2 As[16 * 65];
    __shared__ float2 Bs[16 * 64];
    int t = threadIdx.x, tx = t & 15, ty = t >> 4;
    float2 c[4][4] = {};
    for (int kc = 0; kc < 64; kc += 16) {
        {
            int kk = t & 15, r0 = t >> 4;
#pragma unroll
            for (int p = 0; p < 4; ++p)
                As[kk * 65 + r0 + 16 * p] = g_xhat[(l * 128 + row0 + r0 + 16 * p) * 64 + kc + kk];
        }
        {
            int cc = t & 63, kb = t >> 6;
#pragma unroll
            for (int p = 0; p < 4; ++p)
                Bs[(kb + 4 * p) * 64 + cc] = g_khc[((l * 31 + nd) * 64 + kc + kb + 4 * p) * 128 + o0 + cc];
        }
        __syncthreads();
#pragma unroll
        for (int kk = 0; kk < 16; ++kk) {
            float2 a[4], bv[4];
#pragma unroll
            for (int i = 0; i < 4; ++i) a[i] = As[kk * 65 + ty + 16 * i];
#pragma unroll
            for (int j = 0; j < 4; ++j) bv[j] = Bs[kk * 64 + tx + 16 * j];
#pragma unroll
            for (int i = 0; i < 4; ++i)
#pragma unroll
                for (int j = 0; j < 4; ++j) cfma(c[i][j], a[i], bv[j]);
        }
        __syncthreads();
    }
#pragma unroll
    for (int i = 0; i < 4; ++i) {
        int R = row0 + ty + 16 * i;
        if (R < rows) {
            int base = ((l * 16 + (R >> 3)) * 31 + nd) * 1024 + (R & 7) * 128 + o0;
#pragma unroll
            for (int j = 0; j < 4; ++j) g_z[base + tx + 16 * j] = c[i][j];
        }
    }
}

// ---------------- KD: fmn = sum_l D2 * z, lmin-templated sparsity -------------
template<int LMIN>
__device__ __forceinline__ void kd_body(const float* __restrict__ Ds,
                                        int bo0, int nd, int mi, int t) {
    constexpr int NLz = 16 - LMIN;
    float2 zr[NLz];
#pragma unroll
    for (int u = 0; u < NLz; ++u)
        zr[u] = g_z[(((LMIN + u) * 16 + mi) * 31 + nd) * 1024 + bo0 + t];
    int bo = bo0 + t;
    int baseq = ((bo >> 2) * 16 + mi) * 124 + nd * 4 + (bo & 3);
    for (int k = 0; k < 32; ++k) {
        float2 acc = make_float2(0.f, 0.f);
#pragma unroll
        for (int u = 0; u < NLz; ++u) {
            float d = Ds[k * 16 + LMIN + u];
            acc.x += d * zr[u].x; acc.y += d * zr[u].y;
        }
        g_fmn[k * 507904 + baseq] = acc;
    }
}

__global__ void __launch_bounds__(256) k_d() {
    int bo0 = blockIdx.x * 256, nd = blockIdx.y, mi = blockIdx.z;
    int t = threadIdx.x;
    int n = nd - 15;
    int lmin = max(mi, abs(n));
    __shared__ float Ds[512];
    for (int u = t; u < 512; u += 256)
        Ds[u] = g_D2[((mi + 15) * 31 + nd) * 512 + u];
    __syncthreads();
    switch (lmin) {
        case 0:  kd_body<0>(Ds, bo0, nd, mi, t);  break;
        case 1:  kd_body<1>(Ds, bo0, nd, mi, t);  break;
        case 2:  kd_body<2>(Ds, bo0, nd, mi, t);  break;
        case 3:  kd_body<3>(Ds, bo0, nd, mi, t);  break;
        case 4:  kd_body<4>(Ds, bo0, nd, mi, t);  break;
        case 5:  kd_body<5>(Ds, bo0, nd, mi, t);  break;
        case 6:  kd_body<6>(Ds, bo0, nd, mi, t);  break;
        case 7:  kd_body<7>(Ds, bo0, nd, mi, t);  break;
        case 8:  kd_body<8>(Ds, bo0, nd, mi, t);  break;
        case 9:  kd_body<9>(Ds, bo0, nd, mi, t);  break;
        case 10: kd_body<10>(Ds, bo0, nd, mi, t); break;
        case 11: kd_body<11>(Ds, bo0, nd, mi, t); break;
        case 12: kd_body<12>(Ds, bo0, nd, mi, t); break;
        case 13: kd_body<13>(Ds, bo0, nd, mi, t); break;
        case 14: kd_body<14>(Ds, bo0, nd, mi, t); break;
        default: kd_body<15>(Ds, bo0, nd, mi, t); break;
    }
}

// ---------------- KEF: fused n-DFT (radix-4 over c) + LDS-lean real m-DFT ------
__global__ void __launch_bounds__(256) k_ef(float* __restrict__ out, const float* __restrict__ bias) {
    int boq = blockIdx.x, k = blockIdx.y;
    __shared__ __align__(16) float2 fS[16 * 124];
    __shared__ __align__(16) float2 Hs[4 * 16 * 32];
    __shared__ float2 ES1[31 * 8];       // e^{+2pi i n c/32}, c<8
    __shared__ float2 EBs[16 * 32];
    int t = threadIdx.x;
    {
        const float4* src = (const float4*)(g_fmn + (size_t)(k * 256 + boq) * 1984);
        float4* dst = (float4*)fS;
        for (int u = t; u < 992; u += 256) dst[u] = src[u];
    }
    for (int u = t; u < 248; u += 256) {
        int nd = u >> 3, c = u & 7;
        ES1[u] = g_EOUT[nd * 32 + c];
    }
    for (int u = t; u < 512; u += 256) EBs[u] = g_EB[u];
    __syncthreads();
    // stage 1: H[mi][c'] = sum_nd f e_n(c'); c' in {c, c+8, c+16, c+24} via n mod 4 groups
    {
        int mi = t >> 4, q2 = (t >> 3) & 1, c = t & 7;
        float2 G[2][4];
#pragma unroll
        for (int qq = 0; qq < 2; ++qq)
#pragma unroll
            for (int r = 0; r < 4; ++r) G[qq][r] = make_float2(0.f, 0.f);
        const float4* f4 = (const float4*)(fS + mi * 124);
#pragma unroll
        for (int nd = 0; nd < 31; ++nd) {
            float2 e = ES1[nd * 8 + c];
            float4 fv = f4[nd * 2 + q2];        // q = 2*q2, 2*q2+1
            float2 f0 = make_float2(fv.x, fv.y), f1 = make_float2(fv.z, fv.w);
            int r = (nd + 1) & 3;               // i^n = i^r, n = nd-15
            cfma(G[0][r], f0, e);
            cfma(G[1][r], f1, e);
        }
#pragma unroll
        for (int qq = 0; qq < 2; ++qq) {
            int q = q2 * 2 + qq;
            float2 g0 = G[qq][0], g1 = G[qq][1], g2 = G[qq][2], g3 = G[qq][3];
            float2* Hr = &Hs[(q * 16 + mi) * 32];
            Hr[c]      = make_float2(g0.x + g1.x + g2.x + g3.x, g0.y + g1.y + g2.y + g3.y);
            Hr[c + 8]  = make_float2(g0.x - g1.y - g2.x + g3.y, g0.y + g1.x - g2.y - g3.x);
            Hr[c + 16] = make_float2(g0.x - g1.x + g2.x - g3.x, g0.y - g1.y + g2.y - g3.y);
            Hr[c + 24] = make_float2(g0.x + g1.y - g2.x - g3.y, g0.y - g1.x - g2.y + g3.x);
        }
    }
    __syncthreads();
    // stage 2: out[a][c] = sum_mi w_mi Re(H e^{i2pi mi a/32}); a+16 via m-parity
    // 2 c-values per thread (one LDS.128 per mi), 4 a-values (broadcast E loads)
    {
        int ci = t & 15, q = (t >> 4) & 3, ah = t >> 6;   // c = 2ci, 2ci+1; a' = ah*4+jj
        float E0[4] = {}, E1[4] = {}, O0[4] = {}, O1[4] = {};
#pragma unroll
        for (int mi = 0; mi < 16; ++mi) {
            float4 hp = *(const float4*)&Hs[(q * 16 + mi) * 32 + 2 * ci];
#pragma unroll
            for (int jj = 0; jj < 4; ++jj) {
                float2 e = EBs[mi * 32 + ah * 4 + jj];
                float re0 = hp.x * e.x - hp.y * e.y;
                float re1 = hp.z * e.x - hp.w * e.y;
                if (mi & 1) { O0[jj] += re0; O1[jj] += re1; }
                else        { E0[jj] += re0; E1[jj] += re1; }
            }
        }
        int bo = boq * 4 + q;
        float bv = bias[bo & 127];
        size_t base = ((size_t)(bo * 32 + k)) * 1024 + 2 * ci;
#pragma unroll
        for (int jj = 0; jj < 4; ++jj) {
            int a = ah * 4 + jj;
            *(float2*)&out[base + a * 32] =
                make_float2(E0[jj] + O0[jj] + bv, E1[jj] + O1[jj] + bv);
            *(float2*)&out[base + (a + 16) * 32] =
                make_float2(E0[jj] - O0[jj] + bv, E1[jj] - O1[jj] + bv);
        }
    }
}

// ---------------- stream/event fork-join (created at static init) -------------
static cudaStream_t g_s1 = 0;
static cudaEvent_t g_eP0 = 0, g_eTabF = 0, g_eA2 = 0, g_eTabD = 0;
static bool g_streamOK = false;
namespace {
struct StreamInit {
    StreamInit() {
        bool ok = (cudaStreamCreateWithFlags(&g_s1, cudaStreamNonBlocking) == cudaSuccess);
        ok = ok && (cudaEventCreateWithFlags(&g_eP0, cudaEventDisableTiming) == cudaSuccess);
        ok = ok && (cudaEventCreateWithFlags(&g_eTabF, cudaEventDisableTiming) == cudaSuccess);
        ok = ok && (cudaEventCreateWithFlags(&g_eA2, cudaEventDisableTiming) == cudaSuccess);
        ok = ok && (cudaEventCreateWithFlags(&g_eTabD, cudaEventDisableTiming) == cudaSuccess);
        g_streamOK = ok;
    }
};
static StreamInit g_streamInit;
}

// ---------------- launch ----------------
extern "C" void kernel_launch(void* const* d_in, const int* in_sizes, int n_in,
                              void* d_out, int out_size) {
    const float* x    = (const float*)d_in[0];
    const float* ker  = (const float*)d_in[1];
    const float* bias = (const float*)d_in[2];
    float* out = (float*)d_out;

    if (g_streamOK) {
        // main: p0 -> tabF -> b -> [wait a2] c -> [wait tabD] d -> ef
        // s1:   [wait p0] a1 -> [wait tabF] a2 -> tabD
        k_p0<<<1, 256>>>();
        cudaEventRecord(g_eP0, 0);
        cudaStreamWaitEvent(g_s1, g_eP0, 0);
        k_a1<<<512, 256, 0, g_s1>>>(x);
        k_tabF<<<126, 256>>>();
        cudaEventRecord(g_eTabF, 0);
        cudaStreamWaitEvent(g_s1, g_eTabF, 0);
        k_a2<<<dim3(16, 8), 256, 0, g_s1>>>();
        cudaEventRecord(g_eA2, g_s1);
        k_tabD<<<992, 256, 0, g_s1>>>();
        cudaEventRecord(g_eTabD, g_s1);
        k_b<<<128, 256>>>(ker);
        cudaStreamWaitEvent(0, g_eA2, 0);
        k_c<<<dim3(62, 2, 16), 256>>>();
        cudaStreamWaitEvent(0, g_eTabD, 0);
        k_d<<<dim3(4, 31, 16), 256>>>();
        k_ef<<<dim3(256, 32), 256>>>(out, bias);
    } else {
        k_p0<<<1, 256>>>();
        k_tabF<<<126, 256>>>();
        k_tabD<<<992, 256>>>();
        k_a1<<<512, 256>>>(x);
        k_a2<<<dim3(16, 8), 256>>>();
        k_b<<<128, 256>>>(ker);
        k_c<<<dim3(62, 2, 16), 256>>>();
        k_d<<<dim3(4, 31, 16), 256>>>();
        k_ef<<<dim3(256, 32), 256>>>(out, bias);
    }
    (void)in_sizes; (void)n_in; (void)out_size;
}